// round 11
// baseline (speedup 1.0000x reference)
#include <cuda_runtime.h>
#include <cstdint>

// ---------------------------------------------------------------------------
// LearnableWaveletTransform, fused + register-tiled, with TMA bulk stores:
// results staged in smem, written to gmem via cp.async.bulk (no per-warp STG
// LSU cost for 5 of the 6 output slots).
//
//   x: [B=8, S=4096, F=128] f32  ->  out: [6, B, 4096, F] f32
//   slots: [lo3, hi1, hi2, hi3, hi1+hi2+hi3, lo3]
//
//   hi1[s] = sum_{j<8}  Khi[j]  * x[2s-6  + j]      (s < 2051)
//   hi2[s] = sum_{j<22} C2hi[j] * x[4s-18 + j]      (s < 1029)
//   lo3[s] = sum_{j<50} C3lo[j] * x[8s-42 + j]      (s < 518)   (hi3 same taps)
// ---------------------------------------------------------------------------

#define NB     8
#define S0     4096
#define F4     32                          // 128 floats = 32 float4
#define SLOTSZ ((size_t)NB * S0 * F4)      // float4 elems per output slot
#define RT     4                           // s positions per thread
#define WPB    4                           // warps per block
#define TS     (WPB * RT)                  // s positions per block = 16

struct Filt {
    float Klo[8], Khi[8], C2lo[22], C2hi[22], C3lo[50], C3hi[50];
    constexpr Filt()
        : Klo{ 0.23037781330885523f,  0.7148465705525415f,   0.6308807679295904f,
              -0.02798376941698385f, -0.18703481171888114f,  0.030841381835986965f,
               0.032883011666982945f, -0.010597401784997278f },
          Khi{ -0.010597401784997278f, 0.032883011666982945f, 0.030841381835986965f,
                0.18703481171888114f, -0.02798376941698385f, -0.6308807679295904f,
                0.7148465705525415f,  -0.23037781330885523f },
          C2lo{}, C2hi{}, C3lo{}, C3hi{} {
        for (int j = 0; j < 22; ++j) {
            float alo = 0.f, ahi = 0.f;
            for (int u = 0; u < 8; ++u) {
                const int t = j - 2 * u;
                if (t >= 0 && t < 8) { alo += Klo[u] * Klo[t]; ahi += Khi[u] * Klo[t]; }
            }
            C2lo[j] = alo; C2hi[j] = ahi;
        }
        for (int j = 0; j < 50; ++j) {
            float alo = 0.f, ahi = 0.f;
            for (int v = 0; v < 8; ++v) {
                const int t = j - 4 * v;
                if (t >= 0 && t < 22) { alo += Klo[v] * C2lo[t]; ahi += Khi[v] * C2lo[t]; }
            }
            C3lo[j] = alo; C3hi[j] = ahi;
        }
    }
};
__constant__ Filt FF = Filt();

__device__ __forceinline__ void fma4(float4& a, float c, const float4& v) {
    a.x = fmaf(c, v.x, a.x); a.y = fmaf(c, v.y, a.y);
    a.z = fmaf(c, v.z, a.z); a.w = fmaf(c, v.w, a.w);
}
__device__ __forceinline__ void add4(float4& a, const float4& v) {
    a.x += v.x; a.y += v.y; a.z += v.z; a.w += v.w;
}
__device__ __forceinline__ float4 zero4() { return make_float4(0.f, 0.f, 0.f, 0.f); }

#define REGION_F4  (TS * F4)               // 512 float4 = 8 KB per region

__global__ __launch_bounds__(128, 7)
void wavelet_tma_k(const float4* __restrict__ x, float4* __restrict__ out) {
    // 4 regions: 0=lo3, 1=h1, 2=h2, 3=h3  (32 KB)
    __shared__ float4 sm[4 * REGION_F4];

    const int f4  = threadIdx.x;                           // 0..31
    const int syl = threadIdx.y * RT;                      // local s base (0..12)
    const int sb  = blockIdx.x * TS + syl;                 // global first s
    const int b   = blockIdx.y;

    const float4* __restrict__ xb = x + (size_t)b * (S0 * F4) + f4;
    const size_t obase = ((size_t)(b * S0 + sb)) * F4 + f4;

    float4 hf[RT];
#pragma unroll
    for (int r = 0; r < RT; ++r) hf[r] = zero4();

    // -------- level 3: lo3 -> region 0 ; hi3 -> region 3 (len 518) --------
    {
        float4 al[RT], ah[RT];
#pragma unroll
        for (int r = 0; r < RT; ++r) { al[r] = zero4(); ah[r] = zero4(); }
        const int base = 8 * sb - 42;                     // span 74
        if (base >= 0 && base + 74 <= S0) {               // interior
#pragma unroll
            for (int k = 0; k < 74; ++k) {
                const float4 v = __ldg(xb + (size_t)(base + k) * F4);
#pragma unroll
                for (int r = 0; r < RT; ++r) {
                    const int j = k - 8 * r;
                    if (j >= 0 && j < 50) {
                        fma4(al[r], FF.C3lo[j], v);
                        fma4(ah[r], FF.C3hi[j], v);
                    }
                }
            }
        } else if (sb < 518) {                            // boundary
#pragma unroll
            for (int k = 0; k < 74; ++k) {
                const int xs = base + k;
                if (xs >= 0 && xs < S0) {
                    const float4 v = __ldg(xb + (size_t)xs * F4);
#pragma unroll
                    for (int r = 0; r < RT; ++r) {
                        const int j = k - 8 * r;
                        if (j >= 0 && j < 50 && (sb + r) < 518) {
                            fma4(al[r], FF.C3lo[j], v);
                            fma4(ah[r], FF.C3hi[j], v);
                        }
                    }
                }
            }
        }
#pragma unroll
        for (int r = 0; r < RT; ++r) {
            sm[0 * REGION_F4 + (syl + r) * F4 + f4] = al[r];
            sm[3 * REGION_F4 + (syl + r) * F4 + f4] = ah[r];
            add4(hf[r], ah[r]);
        }
    }

    // ---------------- level 2: hi2 -> region 2 (len 1029) ----------------
    {
        float4 acc[RT];
#pragma unroll
        for (int r = 0; r < RT; ++r) acc[r] = zero4();
        const int base = 4 * sb - 18;                     // span 34
        if (base >= 0 && base + 34 <= S0) {               // interior
#pragma unroll
            for (int k = 0; k < 34; ++k) {
                const float4 v = __ldg(xb + (size_t)(base + k) * F4);
#pragma unroll
                for (int r = 0; r < RT; ++r) {
                    const int j = k - 4 * r;
                    if (j >= 0 && j < 22) fma4(acc[r], FF.C2hi[j], v);
                }
            }
        } else if (sb < 1029) {                           // boundary
#pragma unroll
            for (int k = 0; k < 34; ++k) {
                const int xs = base + k;
                if (xs >= 0 && xs < S0) {
                    const float4 v = __ldg(xb + (size_t)xs * F4);
#pragma unroll
                    for (int r = 0; r < RT; ++r) {
                        const int j = k - 4 * r;
                        if (j >= 0 && j < 22 && (sb + r) < 1029)
                            fma4(acc[r], FF.C2hi[j], v);
                    }
                }
            }
        }
#pragma unroll
        for (int r = 0; r < RT; ++r) {
            sm[2 * REGION_F4 + (syl + r) * F4 + f4] = acc[r];
            add4(hf[r], acc[r]);
        }
    }

    // ---------------- level 1: hi1 -> region 1 (len 2051) ----------------
    {
        float4 acc[RT];
#pragma unroll
        for (int r = 0; r < RT; ++r) acc[r] = zero4();
        const int base = 2 * sb - 6;                      // span 14
        if (base >= 0 && base + 14 <= S0) {               // interior
#pragma unroll
            for (int k = 0; k < 14; ++k) {
                const float4 v = __ldg(xb + (size_t)(base + k) * F4);
#pragma unroll
                for (int r = 0; r < RT; ++r) {
                    const int j = k - 2 * r;
                    if (j >= 0 && j < 8) fma4(acc[r], FF.Khi[j], v);
                }
            }
        } else if (sb < 2051) {                           // boundary
#pragma unroll
            for (int k = 0; k < 14; ++k) {
                const int xs = base + k;
                if (xs >= 0 && xs < S0) {
                    const float4 v = __ldg(xb + (size_t)xs * F4);
#pragma unroll
                    for (int r = 0; r < RT; ++r) {
                        const int j = k - 2 * r;
                        if (j >= 0 && j < 8 && (sb + r) < 2051)
                            fma4(acc[r], FF.Khi[j], v);
                    }
                }
            }
        }
#pragma unroll
        for (int r = 0; r < RT; ++r) {
            sm[1 * REGION_F4 + (syl + r) * F4 + f4] = acc[r];
            add4(hf[r], acc[r]);
        }
    }

    // ---------------- slot 4 (hf) via regular streaming STG ----------------
#pragma unroll
    for (int r = 0; r < RT; ++r)
        __stcs(out + 4 * SLOTSZ + obase + (size_t)r * F4, hf[r]);

    __syncthreads();

    // ------------- bulk-store the 4 regions to 5 slots (0,1,2,3,5) --------
    if (threadIdx.x == 0 && threadIdx.y == 0) {
        asm volatile("fence.proxy.async.shared::cta;" ::: "memory");

        uint32_t sbase;
        asm("{ .reg .u64 t; cvta.to.shared.u64 t, %1; cvt.u32.u64 %0, t; }"
            : "=r"(sbase) : "l"((const void*)sm));

        const size_t blk_off = ((size_t)(b * S0 + blockIdx.x * TS)) * F4;
        const int bytes = REGION_F4 * 16;  // 8192

        // slot <- region : 0<-0, 1<-1, 2<-2, 3<-3, 5<-0
        const float4* dst0 = out + 0 * SLOTSZ + blk_off;
        const float4* dst1 = out + 1 * SLOTSZ + blk_off;
        const float4* dst2 = out + 2 * SLOTSZ + blk_off;
        const float4* dst3 = out + 3 * SLOTSZ + blk_off;
        const float4* dst5 = out + 5 * SLOTSZ + blk_off;

        asm volatile("cp.async.bulk.global.shared::cta.bulk_group [%0], [%1], %2;"
                     :: "l"(dst0), "r"(sbase + 0 * bytes), "r"(bytes) : "memory");
        asm volatile("cp.async.bulk.global.shared::cta.bulk_group [%0], [%1], %2;"
                     :: "l"(dst1), "r"(sbase + 1 * bytes), "r"(bytes) : "memory");
        asm volatile("cp.async.bulk.global.shared::cta.bulk_group [%0], [%1], %2;"
                     :: "l"(dst2), "r"(sbase + 2 * bytes), "r"(bytes) : "memory");
        asm volatile("cp.async.bulk.global.shared::cta.bulk_group [%0], [%1], %2;"
                     :: "l"(dst3), "r"(sbase + 3 * bytes), "r"(bytes) : "memory");
        asm volatile("cp.async.bulk.global.shared::cta.bulk_group [%0], [%1], %2;"
                     :: "l"(dst5), "r"(sbase + 0 * bytes), "r"(bytes) : "memory");
        asm volatile("cp.async.bulk.commit_group;" ::: "memory");
        asm volatile("cp.async.bulk.wait_group.read 0;" ::: "memory");
    }
}

extern "C" void kernel_launch(void* const* d_in, const int* in_sizes, int n_in,
                              void* d_out, int out_size) {
    const float4* x = (const float4*)d_in[0];
    float4* out     = (float4*)d_out;

    const dim3 blk(32, WPB);                     // 128 threads
    wavelet_tma_k<<<dim3(S0 / TS, NB), blk>>>(x, out);
}

// round 12
// speedup vs baseline: 1.2106x; 1.2106x over previous
#include <cuda_runtime.h>

// ---------------------------------------------------------------------------
// LearnableWaveletTransform, fused + register-tiled + per-block s-loop:
// each block owns 64 consecutive s (4 iterations x 16), so the three level
// load windows stay L1-resident across iterations -> ~5x less L2 read traffic.
//
//   x: [B=8, S=4096, F=128] f32  ->  out: [6, B, 4096, F] f32
//   slots: [lo3, hi1, hi2, hi3, hi1+hi2+hi3, lo3]
//
//   hi1[s] = sum_{j<8}  Khi[j]  * x[2s-6  + j]      (s < 2051)
//   hi2[s] = sum_{j<22} C2hi[j] * x[4s-18 + j]      (s < 1029)
//   lo3[s] = sum_{j<50} C3lo[j] * x[8s-42 + j]      (s < 518)   (hi3 same taps)
// ---------------------------------------------------------------------------

#define NB     8
#define S0     4096
#define F4     32                          // 128 floats = 32 float4
#define SLOTSZ ((size_t)NB * S0 * F4)      // float4 elems per output slot
#define RT     4                           // s positions per thread per iter
#define WPB    4                           // warps per block
#define CHUNK  (WPB * RT)                  // 16 s per iteration
#define NITER  4                           // iterations per block
#define TS     (CHUNK * NITER)             // 64 s per block

struct Filt {
    float Klo[8], Khi[8], C2lo[22], C2hi[22], C3lo[50], C3hi[50];
    constexpr Filt()
        : Klo{ 0.23037781330885523f,  0.7148465705525415f,   0.6308807679295904f,
              -0.02798376941698385f, -0.18703481171888114f,  0.030841381835986965f,
               0.032883011666982945f, -0.010597401784997278f },
          Khi{ -0.010597401784997278f, 0.032883011666982945f, 0.030841381835986965f,
                0.18703481171888114f, -0.02798376941698385f, -0.6308807679295904f,
                0.7148465705525415f,  -0.23037781330885523f },
          C2lo{}, C2hi{}, C3lo{}, C3hi{} {
        for (int j = 0; j < 22; ++j) {
            float alo = 0.f, ahi = 0.f;
            for (int u = 0; u < 8; ++u) {
                const int t = j - 2 * u;
                if (t >= 0 && t < 8) { alo += Klo[u] * Klo[t]; ahi += Khi[u] * Klo[t]; }
            }
            C2lo[j] = alo; C2hi[j] = ahi;
        }
        for (int j = 0; j < 50; ++j) {
            float alo = 0.f, ahi = 0.f;
            for (int v = 0; v < 8; ++v) {
                const int t = j - 4 * v;
                if (t >= 0 && t < 22) { alo += Klo[v] * C2lo[t]; ahi += Khi[v] * C2lo[t]; }
            }
            C3lo[j] = alo; C3hi[j] = ahi;
        }
    }
};
__constant__ Filt FF = Filt();

__device__ __forceinline__ void fma4(float4& a, float c, const float4& v) {
    a.x = fmaf(c, v.x, a.x); a.y = fmaf(c, v.y, a.y);
    a.z = fmaf(c, v.z, a.z); a.w = fmaf(c, v.w, a.w);
}
__device__ __forceinline__ void add4(float4& a, const float4& v) {
    a.x += v.x; a.y += v.y; a.z += v.z; a.w += v.w;
}
__device__ __forceinline__ float4 zero4() { return make_float4(0.f, 0.f, 0.f, 0.f); }

__global__ __launch_bounds__(128, 8)
void wavelet_loop_k(const float4* __restrict__ x, float4* __restrict__ out) {
    const int f4 = threadIdx.x;                            // 0..31
    const int b  = blockIdx.y;
    const float4* __restrict__ xb = x + (size_t)b * (S0 * F4) + f4;

    for (int it = 0; it < NITER; ++it) {
        const int sb = blockIdx.x * TS + it * CHUNK + threadIdx.y * RT;
        const size_t obase = ((size_t)(b * S0 + sb)) * F4 + f4;

        float4 hf[RT];
#pragma unroll
        for (int r = 0; r < RT; ++r) hf[r] = zero4();

        // ------ level 3: lo3 -> slots 0,5 ; hi3 -> slot 3 (len 518) ------
        {
            float4 al[RT], ah[RT];
#pragma unroll
            for (int r = 0; r < RT; ++r) { al[r] = zero4(); ah[r] = zero4(); }
            const int base = 8 * sb - 42;                 // span 74
            if (base >= 0 && base + 74 <= S0) {           // interior
#pragma unroll
                for (int k = 0; k < 74; ++k) {
                    const float4 v = __ldg(xb + (size_t)(base + k) * F4);
#pragma unroll
                    for (int r = 0; r < RT; ++r) {
                        const int j = k - 8 * r;
                        if (j >= 0 && j < 50) {
                            fma4(al[r], FF.C3lo[j], v);
                            fma4(ah[r], FF.C3hi[j], v);
                        }
                    }
                }
            } else if (sb < 518) {                        // boundary
#pragma unroll
                for (int k = 0; k < 74; ++k) {
                    const int xs = base + k;
                    if (xs >= 0 && xs < S0) {
                        const float4 v = __ldg(xb + (size_t)xs * F4);
#pragma unroll
                        for (int r = 0; r < RT; ++r) {
                            const int j = k - 8 * r;
                            if (j >= 0 && j < 50 && (sb + r) < 518) {
                                fma4(al[r], FF.C3lo[j], v);
                                fma4(ah[r], FF.C3hi[j], v);
                            }
                        }
                    }
                }
            }
#pragma unroll
            for (int r = 0; r < RT; ++r) {
                const size_t o = obase + (size_t)r * F4;
                __stcs(out + 0 * SLOTSZ + o, al[r]);
                __stcs(out + 3 * SLOTSZ + o, ah[r]);
                __stcs(out + 5 * SLOTSZ + o, al[r]);
                add4(hf[r], ah[r]);
            }
        }

        // ---------------- level 2: hi2 -> slot 2 (len 1029) ----------------
        {
            float4 acc[RT];
#pragma unroll
            for (int r = 0; r < RT; ++r) acc[r] = zero4();
            const int base = 4 * sb - 18;                 // span 34
            if (base >= 0 && base + 34 <= S0) {           // interior
#pragma unroll
                for (int k = 0; k < 34; ++k) {
                    const float4 v = __ldg(xb + (size_t)(base + k) * F4);
#pragma unroll
                    for (int r = 0; r < RT; ++r) {
                        const int j = k - 4 * r;
                        if (j >= 0 && j < 22) fma4(acc[r], FF.C2hi[j], v);
                    }
                }
            } else if (sb < 1029) {                       // boundary
#pragma unroll
                for (int k = 0; k < 34; ++k) {
                    const int xs = base + k;
                    if (xs >= 0 && xs < S0) {
                        const float4 v = __ldg(xb + (size_t)xs * F4);
#pragma unroll
                        for (int r = 0; r < RT; ++r) {
                            const int j = k - 4 * r;
                            if (j >= 0 && j < 22 && (sb + r) < 1029)
                                fma4(acc[r], FF.C2hi[j], v);
                        }
                    }
                }
            }
#pragma unroll
            for (int r = 0; r < RT; ++r) {
                __stcs(out + 2 * SLOTSZ + obase + (size_t)r * F4, acc[r]);
                add4(hf[r], acc[r]);
            }
        }

        // ---------------- level 1: hi1 -> slot 1 (len 2051) ----------------
        {
            float4 acc[RT];
#pragma unroll
            for (int r = 0; r < RT; ++r) acc[r] = zero4();
            const int base = 2 * sb - 6;                  // span 14
            if (base >= 0 && base + 14 <= S0) {           // interior
#pragma unroll
                for (int k = 0; k < 14; ++k) {
                    const float4 v = __ldg(xb + (size_t)(base + k) * F4);
#pragma unroll
                    for (int r = 0; r < RT; ++r) {
                        const int j = k - 2 * r;
                        if (j >= 0 && j < 8) fma4(acc[r], FF.Khi[j], v);
                    }
                }
            } else if (sb < 2051) {                       // boundary
#pragma unroll
                for (int k = 0; k < 14; ++k) {
                    const int xs = base + k;
                    if (xs >= 0 && xs < S0) {
                        const float4 v = __ldg(xb + (size_t)xs * F4);
#pragma unroll
                        for (int r = 0; r < RT; ++r) {
                            const int j = k - 2 * r;
                            if (j >= 0 && j < 8 && (sb + r) < 2051)
                                fma4(acc[r], FF.Khi[j], v);
                        }
                    }
                }
            }
#pragma unroll
            for (int r = 0; r < RT; ++r) {
                __stcs(out + 1 * SLOTSZ + obase + (size_t)r * F4, acc[r]);
                add4(hf[r], acc[r]);
            }
        }

        // ---------------- slot 4: hi1 + hi2 + hi3 ----------------
#pragma unroll
        for (int r = 0; r < RT; ++r)
            __stcs(out + 4 * SLOTSZ + obase + (size_t)r * F4, hf[r]);
    }
}

extern "C" void kernel_launch(void* const* d_in, const int* in_sizes, int n_in,
                              void* d_out, int out_size) {
    const float4* x = (const float4*)d_in[0];
    float4* out     = (float4*)d_out;

    const dim3 blk(32, WPB);                     // 128 threads
    wavelet_loop_k<<<dim3(S0 / TS, NB), blk>>>(x, out);
}